// round 1
// baseline (speedup 1.0000x reference)
#include <cuda_runtime.h>

#define SEQ_LEN   2048
#define STATE_LEN 1024
#define N_POI     10000
#define EPS_VAL   1e-6f
#define THREADS   256
#define PER_T     (SEQ_LEN / THREADS)   // 8

__global__ __launch_bounds__(THREADS)
void attn_loc_kernel(const int* __restrict__ his,
                     const int* __restrict__ cur,
                     const float* __restrict__ mat,
                     float* __restrict__ out)
{
    const int row = blockIdx.x;
    const int tid = threadIdx.x;

    const float* __restrict__ mrow = mat + (size_t)__ldg(cur + row) * N_POI;

    // Phase 1: gather + map to energies, track local max
    float v[PER_T];
    float mx = -INFINITY;
#pragma unroll
    for (int k = 0; k < PER_T; k++) {
        const int j = tid + k * THREADS;
        const int c = __ldg(his + j);
        const float d = __ldg(mrow + c);
        const float e = (d != 0.0f) ? (1.0f / d) : EPS_VAL;
        v[k] = e;
        mx = fmaxf(mx, e);
    }

    // Block max reduction
    __shared__ float sred[THREADS / 32];
#pragma unroll
    for (int o = 16; o; o >>= 1)
        mx = fmaxf(mx, __shfl_xor_sync(0xffffffffu, mx, o));
    if ((tid & 31) == 0) sred[tid >> 5] = mx;
    __syncthreads();
    float bmax = sred[0];
#pragma unroll
    for (int w = 1; w < THREADS / 32; w++) bmax = fmaxf(bmax, sred[w]);
    __syncthreads();

    // Phase 2: exp(e - max), local sum
    float sum = 0.0f;
#pragma unroll
    for (int k = 0; k < PER_T; k++) {
        const float e = expf(v[k] - bmax);
        v[k] = e;
        sum += e;
    }

    // Block sum reduction
#pragma unroll
    for (int o = 16; o; o >>= 1)
        sum += __shfl_xor_sync(0xffffffffu, sum, o);
    if ((tid & 31) == 0) sred[tid >> 5] = sum;
    __syncthreads();
    float bsum = 0.0f;
#pragma unroll
    for (int w = 0; w < THREADS / 32; w++) bsum += sred[w];

    // Phase 3: normalize + coalesced store
    const float inv = 1.0f / bsum;
    float* __restrict__ orow = out + (size_t)row * SEQ_LEN;
#pragma unroll
    for (int k = 0; k < PER_T; k++) {
        orow[tid + k * THREADS] = v[k] * inv;
    }
}

extern "C" void kernel_launch(void* const* d_in, const int* in_sizes, int n_in,
                              void* d_out, int out_size)
{
    const int*   his = (const int*)d_in[0];
    const int*   cur = (const int*)d_in[1];
    const float* mat = (const float*)d_in[2];
    float*       out = (float*)d_out;

    attn_loc_kernel<<<STATE_LEN, THREADS>>>(his, cur, mat, out);
}